// round 2
// baseline (speedup 1.0000x reference)
#include <cuda_runtime.h>
#include <cuda_bf16.h>
#include <math.h>

#define BATCH 1024
#define LSEQ  200
#define HDIM  128
#define MAXN  201
#define NNODE 200000
#define SEQ_STRIDE 132   // padded row stride (floats), multiple of 4 for float4

__device__ float g_rnorm[NNODE];

// ---------------------------------------------------------------------------
// K0: per-row normalize of emb_W, write transposed b.T to out, cache 1/(n+eps)
// grid 3125 x 256 threads, 64 rows per block
// ---------------------------------------------------------------------------
__global__ void k_norm_transpose(const float* __restrict__ emb,
                                 float* __restrict__ outB) {
    __shared__ float tile[64 * SEQ_STRIDE];
    int i0 = blockIdx.x * 64;
    int w = threadIdx.x >> 5, lane = threadIdx.x & 31;
    const float4* emb4 = (const float4*)emb;

    #pragma unroll
    for (int rr = 0; rr < 8; rr++) {
        int il = w * 8 + rr;
        int i = i0 + il;
        float4 v = emb4[(size_t)i * 32 + lane];
        float ss = v.x * v.x + v.y * v.y + v.z * v.z + v.w * v.w;
        #pragma unroll
        for (int o = 16; o; o >>= 1) ss += __shfl_xor_sync(0xffffffffu, ss, o);
        float s = 1.0f / (sqrtf(ss) + 1e-12f);
        if (lane == 0) g_rnorm[i] = s;
        float4 r = make_float4(v.x * s, v.y * s, v.z * s, v.w * s);
        *(float4*)&tile[il * SEQ_STRIDE + lane * 4] = r;
    }
    __syncthreads();
    // transposed write: out[c * 199999 + (i-1)], skip global row 0
    for (int idx = threadIdx.x; idx < 8192; idx += 256) {
        int c = idx >> 6, il = idx & 63;
        int gi = i0 + il;
        if (gi >= 1)
            outB[(size_t)c * (NNODE - 1) + (gi - 1)] = tile[il * SEQ_STRIDE + c];
    }
}

// ---------------------------------------------------------------------------
// K1: fully fused a-path, one block per batch, 512 threads, ~150KB dyn smem
// ---------------------------------------------------------------------------
__global__ void __launch_bounds__(512, 1) k_fused(
    const int* __restrict__ alias_, const int* __restrict__ items,
    const int* __restrict__ mask, const float* __restrict__ emb,
    const float* __restrict__ W0, const float* __restrict__ b0,
    const float* __restrict__ W1, const float* __restrict__ b1,
    const float* __restrict__ W2, const float* __restrict__ b2,
    const float* __restrict__ Wq, const float* __restrict__ bq,
    const float* __restrict__ Wt, const float* __restrict__ bt,
    const float* __restrict__ ln_g, const float* __restrict__ ln_b,
    float* __restrict__ outA)
{
    extern __shared__ float sm[];
    float* s_seq   = sm;                    // 200*132 = 26400
    float* s_ht    = s_seq + LSEQ * SEQ_STRIDE; // 128
    float* s_hts   = s_ht + 128;            // 128
    float* s_q0    = s_hts + 128;           // 128
    float* s_V     = s_q0 + 128;            // 64*128 = 8192
    float* s_vb    = s_V + 8192;            // 64
    float* s_alpha = s_vb + 64;             // 200*8 = 1600
    float* s_mask  = s_alpha + 1600;        // 200
    float* s_S     = s_mask + 200;          // 8*128 = 1024
    float* s_T     = s_S + 1024;            // 8
    float* s_den   = s_T + 8;               // 8
    float* s_cat   = s_den + 8;             // 256  (a_ln | ht)
    float* s_f     = s_cat + 256;           // 128  (temp a, then final f)
    __shared__ int s_len;

    int b = blockIdx.x;
    int tid = threadIdx.x;
    int w = tid >> 5, lane = tid & 31;

    // ---- length + mask ----
    if (tid == 0) s_len = 0;
    __syncthreads();
    if (tid < LSEQ) {
        int m = mask[b * LSEQ + tid];
        s_mask[tid] = (float)m;
        atomicAdd(&s_len, m);
    }
    __syncthreads();
    int len = s_len;

    // ---- gather seq rows (normalized emb rows; zero when masked) ----
    const float4* emb4 = (const float4*)emb;
    for (int l = w; l < LSEQ; l += 16) {
        int item = items[b * MAXN + alias_[b * LSEQ + l]];
        float s = (l < len) ? g_rnorm[item] : 0.0f;
        float4 v = emb4[(size_t)item * 32 + lane];
        float4 r = make_float4(v.x * s, v.y * s, v.z * s, v.w * s);
        *(float4*)&s_seq[l * SEQ_STRIDE + lane * 4] = r;
        if (l == len - 1) *(float4*)&s_ht[lane * 4] = r;
    }
    __syncthreads();

    // ---- hts = elementwise sign-ish of (ht @ Wq^T + bq) ----
    for (int o = w; o < HDIM; o += 16) {
        float4 wv = ((const float4*)(Wq + o * HDIM))[lane];
        float4 xv = ((const float4*)s_ht)[lane];
        float p = wv.x * xv.x + wv.y * xv.y + wv.z * xv.z + wv.w * xv.w;
        #pragma unroll
        for (int off = 16; off; off >>= 1) p += __shfl_xor_sync(0xffffffffu, p, off);
        if (lane == 0) {
            float t = p + bq[o];
            s_hts[o] = t / (fabsf(t) + 1e-12f);
        }
    }
    __syncthreads();

    // ---- q0 = hts @ W0^T + b0 ----
    for (int o = w; o < HDIM; o += 16) {
        float4 wv = ((const float4*)(W0 + o * HDIM))[lane];
        float4 xv = ((const float4*)s_hts)[lane];
        float p = wv.x * xv.x + wv.y * xv.y + wv.z * xv.z + wv.w * xv.w;
        #pragma unroll
        for (int off = 16; off; off >>= 1) p += __shfl_xor_sync(0xffffffffu, p, off);
        if (lane == 0) s_q0[o] = p + b0[o];
    }
    __syncthreads();

    // ---- V[h][j][c] = sum_d q0[h*16+d] * W1[j*16+d, c]; vb analog with b1 ----
    for (int idx = tid; idx < 8192; idx += 512) {
        int hj = idx >> 7, c = idx & 127;
        int h = hj >> 3, j = hj & 7;
        float acc = 0.0f;
        #pragma unroll
        for (int d = 0; d < 16; d++)
            acc += s_q0[h * 16 + d] * W1[(j * 16 + d) * HDIM + c];
        s_V[hj * HDIM + c] = acc;
    }
    if (tid < 64) {
        int h = tid >> 3, j = tid & 7;
        float acc = 0.0f;
        #pragma unroll
        for (int d = 0; d < 16; d++)
            acc += s_q0[h * 16 + d] * b1[j * 16 + d];
        s_vb[tid] = acc;
    }
    __syncthreads();

    // ---- alpha: e[l,h] = exp(2*sigmoid(seq[25h+l/8]·V[h][l%8] + vb)) ----
    for (int t = w; t < 1600; t += 16) {
        int h = t / 200, l = t % 200;
        int r = 25 * h + (l >> 3), j = l & 7;
        const float4* sr = (const float4*)&s_seq[r * SEQ_STRIDE];
        const float4* vr = (const float4*)&s_V[(h * 8 + j) * HDIM];
        float4 a4 = sr[lane], v4 = vr[lane];
        float p = a4.x * v4.x + a4.y * v4.y + a4.z * v4.z + a4.w * v4.w;
        #pragma unroll
        for (int off = 16; off; off >>= 1) p += __shfl_xor_sync(0xffffffffu, p, off);
        if (lane == 0) {
            float x = p + s_vb[h * 8 + j];
            float sg = 1.0f / (1.0f + expf(-x));
            s_alpha[l * 8 + h] = expf(2.0f * sg);
        }
    }
    __syncthreads();

    // ---- softmax denominators over all l (unmasked, per reference) ----
    if (w < 8) {
        float p = 0.0f;
        for (int l = lane; l < LSEQ; l += 32) p += s_alpha[l * 8 + w];
        #pragma unroll
        for (int off = 16; off; off >>= 1) p += __shfl_xor_sync(0xffffffffu, p, off);
        if (lane == 0) s_den[w] = p;
    }
    __syncthreads();

    // ---- scale + apply mask ----
    for (int idx = tid; idx < 1600; idx += 512) {
        int l = idx >> 3, h = idx & 7;
        s_alpha[idx] = s_alpha[idx] / s_den[h] * s_mask[l];
    }
    __syncthreads();

    // ---- T[h] = sum_l alpha_masked ----
    if (w < 8) {
        float p = 0.0f;
        for (int l = lane; l < LSEQ; l += 32) p += s_alpha[l * 8 + w];
        #pragma unroll
        for (int off = 16; off; off >>= 1) p += __shfl_xor_sync(0xffffffffu, p, off);
        if (lane == 0) s_T[w] = p;
    }
    __syncthreads();

    // ---- S[h][k] = sum_l alpha[l,h] * seq[l,k] ----
    for (int idx = tid; idx < 1024; idx += 512) {
        int h = idx >> 7, k = idx & 127;
        float acc = 0.0f;
        for (int l = 0; l < LSEQ; l++)
            acc += s_alpha[l * 8 + h] * s_seq[l * SEQ_STRIDE + k];
        s_S[idx] = acc;
    }
    __syncthreads();

    // ---- a[c] = W2[c,:]·S[c/16,:] + b2[c]*T[c/16]  (store to s_f temp) ----
    for (int c = w; c < HDIM; c += 16) {
        const float4* wr = (const float4*)(W2 + c * HDIM);
        const float4* sr = (const float4*)&s_S[(c >> 4) * HDIM];
        float4 a4 = sr[lane], v4 = wr[lane];
        float p = a4.x * v4.x + a4.y * v4.y + a4.z * v4.z + a4.w * v4.w;
        #pragma unroll
        for (int off = 16; off; off >>= 1) p += __shfl_xor_sync(0xffffffffu, p, off);
        if (lane == 0) s_f[c] = p + b2[c] * s_T[c >> 4];
    }
    __syncthreads();

    // ---- LayerNorm into s_cat[0:128]; copy ht into s_cat[128:256] ----
    if (w == 0) {
        float4 v = ((const float4*)s_f)[lane];
        float sum = v.x + v.y + v.z + v.w;
        #pragma unroll
        for (int off = 16; off; off >>= 1) sum += __shfl_xor_sync(0xffffffffu, sum, off);
        float mu = sum * (1.0f / 128.0f);
        float dx = v.x - mu, dy = v.y - mu, dz = v.z - mu, dw = v.w - mu;
        float vs = dx * dx + dy * dy + dz * dz + dw * dw;
        #pragma unroll
        for (int off = 16; off; off >>= 1) vs += __shfl_xor_sync(0xffffffffu, vs, off);
        float rstd = rsqrtf(vs * (1.0f / 128.0f) + 1e-8f);
        int c = lane * 4;
        s_cat[c + 0] = dx * rstd * ln_g[c + 0] + ln_b[c + 0];
        s_cat[c + 1] = dy * rstd * ln_g[c + 1] + ln_b[c + 1];
        s_cat[c + 2] = dz * rstd * ln_g[c + 2] + ln_b[c + 2];
        s_cat[c + 3] = dw * rstd * ln_g[c + 3] + ln_b[c + 3];
    }
    if (w == 1) {
        ((float4*)(s_cat + 128))[lane] = ((const float4*)s_ht)[lane];
    }
    __syncthreads();

    // ---- f[o] = Wt[o,:256]·cat + bt[o] ----
    for (int o = w; o < HDIM; o += 16) {
        const float4* wr = (const float4*)(Wt + o * 256);
        float4 x0 = ((const float4*)s_cat)[lane];
        float4 w0v = wr[lane];
        float4 x1 = ((const float4*)s_cat)[lane + 32];
        float4 w1v = wr[lane + 32];
        float p = x0.x * w0v.x + x0.y * w0v.y + x0.z * w0v.z + x0.w * w0v.w
                + x1.x * w1v.x + x1.y * w1v.y + x1.z * w1v.z + x1.w * w1v.w;
        #pragma unroll
        for (int off = 16; off; off >>= 1) p += __shfl_xor_sync(0xffffffffu, p, off);
        if (lane == 0) s_f[o] = p + bt[o];
    }
    __syncthreads();

    // ---- final normalize + write ----
    if (w == 0) {
        float4 v = ((const float4*)s_f)[lane];
        float ss = v.x * v.x + v.y * v.y + v.z * v.z + v.w * v.w;
        #pragma unroll
        for (int off = 16; off; off >>= 1) ss += __shfl_xor_sync(0xffffffffu, ss, off);
        float rn = 1.0f / (sqrtf(ss) + 1e-12f);
        float4 r = make_float4(v.x * rn, v.y * rn, v.z * rn, v.w * rn);
        ((float4*)(outA + (size_t)b * HDIM))[lane] = r;
    }
}

// ---------------------------------------------------------------------------
extern "C" void kernel_launch(void* const* d_in, const int* in_sizes, int n_in,
                              void* d_out, int out_size) {
    const int*   alias_ = (const int*)d_in[0];
    const int*   items  = (const int*)d_in[1];
    const int*   mask   = (const int*)d_in[2];
    const float* emb    = (const float*)d_in[3];
    const float* W0     = (const float*)d_in[4];
    const float* b0     = (const float*)d_in[5];
    const float* W1     = (const float*)d_in[6];
    const float* b1     = (const float*)d_in[7];
    const float* W2     = (const float*)d_in[8];
    const float* b2     = (const float*)d_in[9];
    const float* Wq     = (const float*)d_in[10];
    const float* bq     = (const float*)d_in[11];
    const float* Wt     = (const float*)d_in[12];
    const float* bt     = (const float*)d_in[13];
    const float* ln_g   = (const float*)d_in[14];
    const float* ln_b   = (const float*)d_in[15];

    float* out  = (float*)d_out;
    float* outA = out;                    // (1024,128)
    float* outB = out + BATCH * HDIM;     // (128,199999)

    // K0: emb row norms + transposed normalized b output
    k_norm_transpose<<<NNODE / 64, 256>>>(emb, outB);

    // K1: fused a-path
    const int smem_bytes = (LSEQ * SEQ_STRIDE + 128 * 3 + 8192 + 64 + 1600 + 200
                            + 1024 + 8 + 8 + 256 + 128) * (int)sizeof(float);
    cudaFuncSetAttribute(k_fused, cudaFuncAttributeMaxDynamicSharedMemorySize,
                         smem_bytes);
    k_fused<<<BATCH, 512, smem_bytes>>>(alias_, items, mask, emb,
                                        W0, b0, W1, b1, W2, b2, Wq, bq,
                                        Wt, bt, ln_g, ln_b, outA);
}

// round 4
// speedup vs baseline: 1.4837x; 1.4837x over previous
#include <cuda_runtime.h>
#include <cuda_bf16.h>
#include <math.h>

#define BATCH 1024
#define LSEQ  200
#define HDIM  128
#define MAXN  201
#define NNODE 200000

__device__ float g_rnorm[NNODE];

// ---------------------------------------------------------------------------
// K0: per-row normalize of emb_W, write transposed b.T, cache 1/(norm+eps).
// 160 rows/block, 1250 blocks, 256 threads. Conflict-free tile (stride 133).
// ---------------------------------------------------------------------------
__global__ void __launch_bounds__(256) k_norm_transpose(
        const float* __restrict__ emb, float* __restrict__ outB) {
    extern __shared__ float tile[];          // 160 * 133 floats
    int i0 = blockIdx.x * 160;
    int w = threadIdx.x >> 5, lane = threadIdx.x & 31;

    #pragma unroll
    for (int rr = 0; rr < 20; rr++) {
        int il = w * 20 + rr;
        int i  = i0 + il;
        const float* row = emb + (size_t)i * HDIM;
        float v0 = row[lane];
        float v1 = row[lane + 32];
        float v2 = row[lane + 64];
        float v3 = row[lane + 96];
        float ss = v0 * v0 + v1 * v1 + v2 * v2 + v3 * v3;
        #pragma unroll
        for (int o = 16; o; o >>= 1) ss += __shfl_xor_sync(0xffffffffu, ss, o);
        float s = 1.0f / (sqrtf(ss) + 1e-12f);
        if (lane == 0) g_rnorm[i] = s;
        float* tr = tile + il * 133;
        tr[lane]      = v0 * s;
        tr[lane + 32] = v1 * s;
        tr[lane + 64] = v2 * s;
        tr[lane + 96] = v3 * s;
    }
    __syncthreads();

    for (int c = w; c < HDIM; c += 8) {
        size_t obase = (size_t)c * (NNODE - 1);
        for (int il = lane; il < 160; il += 32) {
            int gi = i0 + il;
            if (gi >= 1) outB[obase + gi - 1] = tile[il * 133 + c];
        }
    }
}

// ---------------------------------------------------------------------------
// K1: fused a-path, one 256-thread block per batch, ~42.6KB smem (5 CTAs/SM).
// seq never materialized: rows re-gathered from emb (pass B hits L2).
// ---------------------------------------------------------------------------
__global__ void __launch_bounds__(256, 5) k_fused(
    const int* __restrict__ alias_, const int* __restrict__ items,
    const int* __restrict__ mask, const float* __restrict__ emb,
    const float* __restrict__ W0, const float* __restrict__ b0,
    const float* __restrict__ W1, const float* __restrict__ b1,
    const float* __restrict__ W2, const float* __restrict__ b2,
    const float* __restrict__ Wq, const float* __restrict__ bq,
    const float* __restrict__ Wt, const float* __restrict__ bt,
    const float* __restrict__ ln_g, const float* __restrict__ ln_b,
    float* __restrict__ outA)
{
    extern __shared__ float sm[];
    float* s_V    = sm;                 // 8192  (aliased later: s_S/s_cat/s_f)
    float* s_e    = sm + 8192;          // 1600
    float* s_rn   = sm + 9792;          // 200
    int*   s_item = (int*)(sm + 9992);  // 200
    float* s_ht   = sm + 10192;         // 128
    float* s_hts  = sm + 10320;         // 128
    float* s_q0   = sm + 10448;         // 128
    float* s_vb   = sm + 10576;         // 64
    float* s_den  = sm + 10640;         // 8
    float* s_T    = sm + 10648;         // 8
    // aliases of s_V (V dead after pass A):
    float* s_S    = s_V;                // 1024
    float* s_cat  = s_V + 1024;         // 256
    float* s_f    = s_V + 1280;         // 128
    __shared__ int s_len;

    int b = blockIdx.x;
    int tid = threadIdx.x;
    int w = tid >> 5, lane = tid & 31;

    // ---- len + per-position item / rnorm ----
    if (tid == 0) s_len = 0;
    __syncthreads();
    if (tid < LSEQ) {
        int m = mask[b * LSEQ + tid];
        atomicAdd(&s_len, m);
        int it = items[b * MAXN + alias_[b * LSEQ + tid]];
        s_item[tid] = it;
        s_rn[tid] = g_rnorm[it];
    }
    __syncthreads();
    int len = s_len;

    // ---- ht = normalized last seq row ----
    if (w == 0) {
        int it = s_item[len - 1];
        float s = s_rn[len - 1];
        float4 v = ((const float4*)emb)[(size_t)it * 32 + lane];
        *(float4*)&s_ht[lane * 4] =
            make_float4(v.x * s, v.y * s, v.z * s, v.w * s);
    }
    __syncthreads();

    // ---- hts[o] = sign-ish(ht . Wq[o] + bq[o]) ----
    for (int o = w; o < HDIM; o += 8) {
        float4 wv = ((const float4*)(Wq + o * HDIM))[lane];
        float4 xv = ((const float4*)s_ht)[lane];
        float p = wv.x * xv.x + wv.y * xv.y + wv.z * xv.z + wv.w * xv.w;
        #pragma unroll
        for (int off = 16; off; off >>= 1) p += __shfl_xor_sync(0xffffffffu, p, off);
        if (lane == 0) {
            float t = p + bq[o];
            s_hts[o] = t / (fabsf(t) + 1e-12f);
        }
    }
    __syncthreads();

    // ---- q0 = hts @ W0^T + b0 ----
    for (int o = w; o < HDIM; o += 8) {
        float4 wv = ((const float4*)(W0 + o * HDIM))[lane];
        float4 xv = ((const float4*)s_hts)[lane];
        float p = wv.x * xv.x + wv.y * xv.y + wv.z * xv.z + wv.w * xv.w;
        #pragma unroll
        for (int off = 16; off; off >>= 1) p += __shfl_xor_sync(0xffffffffu, p, off);
        if (lane == 0) s_q0[o] = p + b0[o];
    }
    __syncthreads();

    // ---- V[h][j][c] = sum_d q0[h*16+d]*W1[j*16+d, c]; W1 loads shared over h ----
    for (int p = tid; p < 1024; p += 256) {       // p = (j, c)
        int j = p >> 7, c = p & 127;
        float w1d[16];
        #pragma unroll
        for (int d = 0; d < 16; d++) w1d[d] = W1[(j * 16 + d) * HDIM + c];
        #pragma unroll
        for (int h = 0; h < 8; h++) {
            float acc = 0.0f;
            #pragma unroll
            for (int d = 0; d < 16; d++) acc += s_q0[h * 16 + d] * w1d[d];
            s_V[(h * 8 + j) * HDIM + c] = acc;
        }
    }
    if (tid < 64) {
        int h = tid >> 3, j = tid & 7;
        float acc = 0.0f;
        #pragma unroll
        for (int d = 0; d < 16; d++) acc += s_q0[h * 16 + d] * b1[j * 16 + d];
        s_vb[tid] = acc;
    }
    __syncthreads();

    // ---- pass A: e[l,h] = exp(2*sigmoid(seq[25h+l/8] . V[h][l%8] + vb)) ----
    for (int r = w; r < LSEQ; r += 8) {
        float4 v = make_float4(0.f, 0.f, 0.f, 0.f);
        if (r < len) {
            float s = s_rn[r];
            float4 g = ((const float4*)emb)[(size_t)s_item[r] * 32 + lane];
            v = make_float4(g.x * s, g.y * s, g.z * s, g.w * s);
        }
        int h = r / 25;
        int bl = (r - h * 25) * 8;
        float p[8];
        #pragma unroll
        for (int j = 0; j < 8; j++) {
            float4 u = *(const float4*)&s_V[(h * 8 + j) * HDIM + lane * 4];
            p[j] = v.x * u.x + v.y * u.y + v.z * u.z + v.w * u.w;
        }
        #pragma unroll
        for (int j = 0; j < 8; j++) {
            #pragma unroll
            for (int off = 16; off; off >>= 1)
                p[j] += __shfl_xor_sync(0xffffffffu, p[j], off);
        }
        if (lane == 0) {
            #pragma unroll
            for (int j = 0; j < 8; j++) {
                float x = p[j] + s_vb[h * 8 + j];
                float sg = 1.0f / (1.0f + expf(-x));
                s_e[(bl + j) * 8 + h] = expf(2.0f * sg);
            }
        }
    }
    __syncthreads();

    // ---- softmax denominators (over all l, unmasked) ----
    if (w < 8) {
        float p = 0.0f;
        for (int l = lane; l < LSEQ; l += 32) p += s_e[l * 8 + w];
        #pragma unroll
        for (int off = 16; off; off >>= 1) p += __shfl_xor_sync(0xffffffffu, p, off);
        if (lane == 0) s_den[w] = 1.0f / p;
    }
    __syncthreads();

    // ---- em[l,h] = e/den * mask  (mask == l < len) ----
    for (int idx = tid; idx < 1600; idx += 256) {
        int l = idx >> 3, h = idx & 7;
        float m = (l < len) ? 1.0f : 0.0f;
        s_e[idx] = s_e[idx] * s_den[h] * m;
    }
    __syncthreads();

    // ---- T[h] = sum_l em ----
    if (w < 8) {
        float p = 0.0f;
        for (int l = lane; l < len; l += 32) p += s_e[l * 8 + w];
        #pragma unroll
        for (int off = 16; off; off >>= 1) p += __shfl_xor_sync(0xffffffffu, p, off);
        if (lane == 0) s_T[w] = p;
    }
    __syncthreads();

    // ---- pass B: S[h,k] = sum_l em[l,h] * rn[l] * emb[item_l, k] ----
    {
        int kk  = (w & 3) * 32 + lane;   // 0..127
        int par = w >> 2;                // l parity split across warp groups
        float acc[8];
        #pragma unroll
        for (int h = 0; h < 8; h++) acc[h] = 0.0f;
        #pragma unroll 2
        for (int l = par; l < len; l += 2) {
            float u = __ldg(&emb[(size_t)s_item[l] * HDIM + kk]) * s_rn[l];
            #pragma unroll
            for (int h = 0; h < 8; h++) acc[h] += s_e[l * 8 + h] * u;
        }
        __syncthreads();   // all reads of s_V (pass A) done; s_S aliases s_V
        if (par == 0) {
            #pragma unroll
            for (int h = 0; h < 8; h++) s_S[h * HDIM + kk] = acc[h];
        }
        __syncthreads();
        if (par == 1) {
            #pragma unroll
            for (int h = 0; h < 8; h++) s_S[h * HDIM + kk] += acc[h];
        }
        __syncthreads();
    }

    // ---- a[c] = W2[c,:] . S[c/16,:] + b2[c]*T[c/16]  -> s_f ----
    for (int c = w; c < HDIM; c += 8) {
        float4 wv = ((const float4*)(W2 + c * HDIM))[lane];
        float4 sv = *(const float4*)&s_S[(c >> 4) * HDIM + lane * 4];
        float p = wv.x * sv.x + wv.y * sv.y + wv.z * sv.z + wv.w * sv.w;
        #pragma unroll
        for (int off = 16; off; off >>= 1) p += __shfl_xor_sync(0xffffffffu, p, off);
        if (lane == 0) s_f[c] = p + b2[c] * s_T[c >> 4];
    }
    __syncthreads();

    // ---- LayerNorm -> s_cat[0:128]; ht -> s_cat[128:256] ----
    if (w == 0) {
        float4 v = ((const float4*)s_f)[lane];
        float sum = v.x + v.y + v.z + v.w;
        #pragma unroll
        for (int off = 16; off; off >>= 1) sum += __shfl_xor_sync(0xffffffffu, sum, off);
        float mu = sum * (1.0f / 128.0f);
        float dx = v.x - mu, dy = v.y - mu, dz = v.z - mu, dw = v.w - mu;
        float vs = dx * dx + dy * dy + dz * dz + dw * dw;
        #pragma unroll
        for (int off = 16; off; off >>= 1) vs += __shfl_xor_sync(0xffffffffu, vs, off);
        float rstd = rsqrtf(vs * (1.0f / 128.0f) + 1e-8f);
        int c = lane * 4;
        s_cat[c + 0] = dx * rstd * ln_g[c + 0] + ln_b[c + 0];
        s_cat[c + 1] = dy * rstd * ln_g[c + 1] + ln_b[c + 1];
        s_cat[c + 2] = dz * rstd * ln_g[c + 2] + ln_b[c + 2];
        s_cat[c + 3] = dw * rstd * ln_g[c + 3] + ln_b[c + 3];
    }
    if (w == 1) {
        ((float4*)(s_cat + 128))[lane] = ((const float4*)s_ht)[lane];
    }
    __syncthreads();

    // ---- f[o] = Wt[o,:256] . cat + bt[o] ----
    for (int o = w; o < HDIM; o += 8) {
        const float4* wr = (const float4*)(Wt + o * 256);
        float4 x0 = ((const float4*)s_cat)[lane];
        float4 w0v = wr[lane];
        float4 x1 = ((const float4*)s_cat)[lane + 32];
        float4 w1v = wr[lane + 32];
        float p = x0.x * w0v.x + x0.y * w0v.y + x0.z * w0v.z + x0.w * w0v.w
                + x1.x * w1v.x + x1.y * w1v.y + x1.z * w1v.z + x1.w * w1v.w;
        #pragma unroll
        for (int off = 16; off; off >>= 1) p += __shfl_xor_sync(0xffffffffu, p, off);
        if (lane == 0) s_f[o] = p + bt[o];
    }
    __syncthreads();

    // ---- final normalize + write ----
    if (w == 0) {
        float4 v = ((const float4*)s_f)[lane];
        float ss = v.x * v.x + v.y * v.y + v.z * v.z + v.w * v.w;
        #pragma unroll
        for (int off = 16; off; off >>= 1) ss += __shfl_xor_sync(0xffffffffu, ss, off);
        float rn = 1.0f / (sqrtf(ss) + 1e-12f);
        ((float4*)(outA + (size_t)b * HDIM))[lane] =
            make_float4(v.x * rn, v.y * rn, v.z * rn, v.w * rn);
    }
}

// ---------------------------------------------------------------------------
extern "C" void kernel_launch(void* const* d_in, const int* in_sizes, int n_in,
                              void* d_out, int out_size) {
    const int*   alias_ = (const int*)d_in[0];
    const int*   items  = (const int*)d_in[1];
    const int*   mask   = (const int*)d_in[2];
    const float* emb    = (const float*)d_in[3];
    const float* W0     = (const float*)d_in[4];
    const float* b0     = (const float*)d_in[5];
    const float* W1     = (const float*)d_in[6];
    const float* b1     = (const float*)d_in[7];
    const float* W2     = (const float*)d_in[8];
    const float* b2     = (const float*)d_in[9];
    const float* Wq     = (const float*)d_in[10];
    const float* bq     = (const float*)d_in[11];
    const float* Wt     = (const float*)d_in[12];
    const float* bt     = (const float*)d_in[13];
    const float* ln_g   = (const float*)d_in[14];
    const float* ln_b   = (const float*)d_in[15];

    float* out  = (float*)d_out;
    float* outA = out;                    // (1024,128)
    float* outB = out + BATCH * HDIM;     // (128,199999)

    // K0
    const int k0_smem = 160 * 133 * (int)sizeof(float);   // 85,120 B
    cudaFuncSetAttribute(k_norm_transpose,
                         cudaFuncAttributeMaxDynamicSharedMemorySize, k0_smem);
    k_norm_transpose<<<NNODE / 160, 256, k0_smem>>>(emb, outB);

    // K1
    const int k1_smem = 10656 * (int)sizeof(float);       // 42,624 B
    cudaFuncSetAttribute(k_fused,
                         cudaFuncAttributeMaxDynamicSharedMemorySize, k1_smem);
    k_fused<<<BATCH, 256, k1_smem>>>(alias_, items, mask, emb,
                                     W0, b0, W1, b1, W2, b2, Wq, bq,
                                     Wt, bt, ln_g, ln_b, outA);
}

// round 5
// speedup vs baseline: 2.2489x; 1.5158x over previous
#include <cuda_runtime.h>
#include <cuda_bf16.h>
#include <math.h>

#define BATCH 1024
#define LSEQ  200
#define HDIM  128
#define MAXN  201
#define NNODE 200000
#define STRIDE 132        // padded fp32 row stride (conflict-free, 16B-aligned)

__device__ float g_rnorm[NNODE];

// ---------------------------------------------------------------------------
// K0: row-normalize emb_W, write transposed b.T, cache 1/(norm+eps).
// 64 rows/block (33.8KB smem -> 6 CTAs/SM), 256 threads.
// ---------------------------------------------------------------------------
__global__ void __launch_bounds__(256) k_norm_transpose(
        const float* __restrict__ emb, float* __restrict__ outB) {
    __shared__ float tile[64 * STRIDE];
    int i0 = blockIdx.x * 64;
    int w = threadIdx.x >> 5, lane = threadIdx.x & 31;
    const float4* emb4 = (const float4*)emb;

    #pragma unroll
    for (int rr = 0; rr < 8; rr++) {
        int il = w * 8 + rr;
        int i = i0 + il;
        float4 v = emb4[(size_t)i * 32 + lane];
        float ss = v.x * v.x + v.y * v.y + v.z * v.z + v.w * v.w;
        #pragma unroll
        for (int o = 16; o; o >>= 1) ss += __shfl_xor_sync(0xffffffffu, ss, o);
        float s = 1.0f / (sqrtf(ss) + 1e-12f);
        if (lane == 0) g_rnorm[i] = s;
        *(float4*)&tile[il * STRIDE + lane * 4] =
            make_float4(v.x * s, v.y * s, v.z * s, v.w * s);
    }
    __syncthreads();
    // transposed write: out[c * 199999 + (i-1)], skip global row 0
    for (int idx = threadIdx.x; idx < 8192; idx += 256) {
        int c = idx >> 6, il = idx & 63;
        int gi = i0 + il;
        if (gi >= 1)
            __stcs(&outB[(size_t)c * (NNODE - 1) + (gi - 1)],
                   tile[il * STRIDE + c]);
    }
}

// ---------------------------------------------------------------------------
// K1: fused a-path. 512 threads/block, 97.2KB smem -> 2 CTAs/SM.
// Pass A: shuffle-free dots from a staged 100-row tile (4 heads per round).
// Pass B: one (h, float2-column) per thread, gmem L2 reads.
// ---------------------------------------------------------------------------
__global__ void __launch_bounds__(512, 2) k_fused(
    const int* __restrict__ alias_, const int* __restrict__ items,
    const int* __restrict__ mask, const float* __restrict__ emb,
    const float* __restrict__ W0, const float* __restrict__ b0,
    const float* __restrict__ W1, const float* __restrict__ b1,
    const float* __restrict__ W2, const float* __restrict__ b2,
    const float* __restrict__ Wq, const float* __restrict__ bq,
    const float* __restrict__ Wt, const float* __restrict__ bt,
    const float* __restrict__ ln_g, const float* __restrict__ ln_b,
    float* __restrict__ outA)
{
    extern __shared__ float sm[];
    float* s_tile = sm;                    // 100*132 = 13200
    float* s_V    = sm + 13200;            // 64*132  = 8448
    float* s_e    = sm + 21648;            // 200*9   = 1800
    float* s_rn   = sm + 23448;            // 200
    int*   s_item = (int*)(sm + 23648);    // 200
    float* s_ht   = sm + 23848;            // 128
    float* s_hts  = sm + 23976;            // 128
    float* s_q0   = sm + 24104;            // 128
    float* s_vb   = sm + 24232;            // 64
    float* s_den  = sm + 24296;            // 8
    float* s_T    = sm + 24304;            // 8
    // aliases of s_tile (dead after pass A):
    float* s_S    = s_tile;                // 1024
    float* s_cat  = s_tile + 1024;         // 256
    float* s_f    = s_tile + 1280;         // 128
    __shared__ int s_len;

    int b = blockIdx.x;
    int tid = threadIdx.x;
    int w = tid >> 5, lane = tid & 31;

    // ---- len + per-position item / rnorm ----
    if (tid == 0) s_len = 0;
    __syncthreads();
    if (tid < LSEQ) {
        int m = mask[b * LSEQ + tid];
        atomicAdd(&s_len, m);
        int it = items[b * MAXN + alias_[b * LSEQ + tid]];
        s_item[tid] = it;
        s_rn[tid] = g_rnorm[it];
    }
    __syncthreads();
    int len = s_len;

    // ---- ht = normalized last seq row ----
    if (w == 0) {
        int it = s_item[len - 1];
        float s = s_rn[len - 1];
        float4 v = ((const float4*)emb)[(size_t)it * 32 + lane];
        *(float4*)&s_ht[lane * 4] =
            make_float4(v.x * s, v.y * s, v.z * s, v.w * s);
    }
    __syncthreads();

    // ---- hts[o] = sign-ish(ht . Wq[o] + bq[o]) ----
    for (int o = w; o < HDIM; o += 16) {
        float4 wv = ((const float4*)(Wq + o * HDIM))[lane];
        float4 xv = ((const float4*)s_ht)[lane];
        float p = wv.x * xv.x + wv.y * xv.y + wv.z * xv.z + wv.w * xv.w;
        #pragma unroll
        for (int off = 16; off; off >>= 1) p += __shfl_xor_sync(0xffffffffu, p, off);
        if (lane == 0) {
            float t = p + bq[o];
            s_hts[o] = t / (fabsf(t) + 1e-12f);
        }
    }
    __syncthreads();

    // ---- q0 = hts @ W0^T + b0 ----
    for (int o = w; o < HDIM; o += 16) {
        float4 wv = ((const float4*)(W0 + o * HDIM))[lane];
        float4 xv = ((const float4*)s_hts)[lane];
        float p = wv.x * xv.x + wv.y * xv.y + wv.z * xv.z + wv.w * xv.w;
        #pragma unroll
        for (int off = 16; off; off >>= 1) p += __shfl_xor_sync(0xffffffffu, p, off);
        if (lane == 0) s_q0[o] = p + b0[o];
    }
    __syncthreads();

    // ---- V[h][j][c] = sum_d q0[h*16+d]*W1[j*16+d, c] (stride-132 rows) ----
    for (int p = tid; p < 1024; p += 512) {       // p = (j, c)
        int j = p >> 7, c = p & 127;
        float w1d[16];
        #pragma unroll
        for (int d = 0; d < 16; d++) w1d[d] = W1[(j * 16 + d) * HDIM + c];
        #pragma unroll
        for (int h = 0; h < 8; h++) {
            float acc = 0.0f;
            #pragma unroll
            for (int d = 0; d < 16; d++) acc += s_q0[h * 16 + d] * w1d[d];
            s_V[(h * 8 + j) * STRIDE + c] = acc;
        }
    }
    if (tid < 64) {
        int h = tid >> 3, j = tid & 7;
        float acc = 0.0f;
        #pragma unroll
        for (int d = 0; d < 16; d++) acc += s_q0[h * 16 + d] * b1[j * 16 + d];
        s_vb[tid] = acc;
    }
    __syncthreads();

    // ---- pass A: two rounds of 4 heads; shuffle-free full dots from smem ----
    for (int t = 0; t < 2; t++) {
        // gather 100 rows (warp-per-row, coalesced 512B reads)
        for (int r = w; r < 100; r += 16) {
            int gr = t * 100 + r;
            int it = s_item[gr];
            float s = (gr < len) ? s_rn[gr] : 0.0f;
            float4 v = ((const float4*)emb)[(size_t)it * 32 + lane];
            *(float4*)&s_tile[r * STRIDE + lane * 4] =
                make_float4(v.x * s, v.y * s, v.z * s, v.w * s);
        }
        __syncthreads();
        // 800 outputs (4 heads x 200 l), one per thread (1.56 rounds)
        for (int idx = tid; idx < 800; idx += 512) {
            int hh = idx / 200;           // 0..3 local head
            int l  = idx % 200;
            int h  = t * 4 + hh;
            int j  = l & 7;
            const float4* sr = (const float4*)&s_tile[(hh * 25 + (l >> 3)) * STRIDE];
            const float4* vr = (const float4*)&s_V[(h * 8 + j) * STRIDE];
            float a0 = 0.f, a1 = 0.f, a2 = 0.f, a3 = 0.f;
            #pragma unroll
            for (int k = 0; k < 32; k += 4) {
                float4 x0 = sr[k + 0], y0 = vr[k + 0];
                float4 x1 = sr[k + 1], y1 = vr[k + 1];
                float4 x2 = sr[k + 2], y2 = vr[k + 2];
                float4 x3 = sr[k + 3], y3 = vr[k + 3];
                a0 += x0.x * y0.x + x0.y * y0.y + x0.z * y0.z + x0.w * y0.w;
                a1 += x1.x * y1.x + x1.y * y1.y + x1.z * y1.z + x1.w * y1.w;
                a2 += x2.x * y2.x + x2.y * y2.y + x2.z * y2.z + x2.w * y2.w;
                a3 += x3.x * y3.x + x3.y * y3.y + x3.z * y3.z + x3.w * y3.w;
            }
            float x = (a0 + a1) + (a2 + a3) + s_vb[h * 8 + j];
            float sg = 1.0f / (1.0f + __expf(-x));
            s_e[l * 9 + h] = __expf(2.0f * sg);
        }
        __syncthreads();
    }

    // ---- den (warps 0-7) and masked numerator sum T (warps 8-15), parallel ----
    if (w < 8) {
        float p = 0.0f;
        for (int l = lane; l < LSEQ; l += 32) p += s_e[l * 9 + w];
        #pragma unroll
        for (int off = 16; off; off >>= 1) p += __shfl_xor_sync(0xffffffffu, p, off);
        if (lane == 0) s_den[w] = 1.0f / p;
    } else {
        int hh = w - 8;
        float p = 0.0f;
        for (int l = lane; l < len; l += 32) p += s_e[l * 9 + hh];
        #pragma unroll
        for (int off = 16; off; off >>= 1) p += __shfl_xor_sync(0xffffffffu, p, off);
        if (lane == 0) s_T[hh] = p;
    }
    __syncthreads();
    if (tid < 8) s_T[tid] *= s_den[tid];
    // fold mask * rn[l] * (1/den[h]) into the weights
    for (int idx = tid; idx < 1600; idx += 512) {
        int l = idx >> 3, h = idx & 7;
        float m = (l < len) ? s_rn[l] : 0.0f;
        s_e[l * 9 + h] *= s_den[h] * m;
    }
    __syncthreads();

    // ---- pass B: S[h, 2k] — one (h, float2 column) per thread ----
    {
        int h  = tid >> 6;        // 0..7
        int k2 = tid & 63;        // float2 column
        const float2* emb2 = (const float2*)emb;
        float ax = 0.0f, ay = 0.0f;
        #pragma unroll 4
        for (int l = 0; l < len; l++) {
            float wgt = s_e[l * 9 + h];
            float2 u = __ldg(&emb2[(size_t)s_item[l] * 64 + k2]);
            ax += wgt * u.x;
            ay += wgt * u.y;
        }
        ((float2*)s_S)[h * 64 + k2] = make_float2(ax, ay);
    }
    __syncthreads();

    // ---- a[c] = W2[c,:] . S[c/16,:] + b2[c]*T[c/16]  -> s_f ----
    for (int c = w; c < HDIM; c += 16) {
        float4 wv = ((const float4*)(W2 + c * HDIM))[lane];
        float4 sv = *(const float4*)&s_S[(c >> 4) * HDIM + lane * 4];
        float p = wv.x * sv.x + wv.y * sv.y + wv.z * sv.z + wv.w * sv.w;
        #pragma unroll
        for (int off = 16; off; off >>= 1) p += __shfl_xor_sync(0xffffffffu, p, off);
        if (lane == 0) s_f[c] = p + b2[c] * s_T[c >> 4];
    }
    __syncthreads();

    // ---- LayerNorm -> s_cat[0:128]; ht -> s_cat[128:256] ----
    if (w == 0) {
        float4 v = ((const float4*)s_f)[lane];
        float sum = v.x + v.y + v.z + v.w;
        #pragma unroll
        for (int off = 16; off; off >>= 1) sum += __shfl_xor_sync(0xffffffffu, sum, off);
        float mu = sum * (1.0f / 128.0f);
        float dx = v.x - mu, dy = v.y - mu, dz = v.z - mu, dw = v.w - mu;
        float vs = dx * dx + dy * dy + dz * dz + dw * dw;
        #pragma unroll
        for (int off = 16; off; off >>= 1) vs += __shfl_xor_sync(0xffffffffu, vs, off);
        float rstd = rsqrtf(vs * (1.0f / 128.0f) + 1e-8f);
        int c = lane * 4;
        s_cat[c + 0] = dx * rstd * ln_g[c + 0] + ln_b[c + 0];
        s_cat[c + 1] = dy * rstd * ln_g[c + 1] + ln_b[c + 1];
        s_cat[c + 2] = dz * rstd * ln_g[c + 2] + ln_b[c + 2];
        s_cat[c + 3] = dw * rstd * ln_g[c + 3] + ln_b[c + 3];
    }
    if (w == 1) {
        ((float4*)(s_cat + 128))[lane] = ((const float4*)s_ht)[lane];
    }
    __syncthreads();

    // ---- f[o] = Wt[o,:256] . cat + bt[o] ----
    for (int o = w; o < HDIM; o += 16) {
        const float4* wr = (const float4*)(Wt + o * 256);
        float4 x0 = ((const float4*)s_cat)[lane];
        float4 w0v = wr[lane];
        float4 x1 = ((const float4*)s_cat)[lane + 32];
        float4 w1v = wr[lane + 32];
        float p = x0.x * w0v.x + x0.y * w0v.y + x0.z * w0v.z + x0.w * w0v.w
                + x1.x * w1v.x + x1.y * w1v.y + x1.z * w1v.z + x1.w * w1v.w;
        #pragma unroll
        for (int off = 16; off; off >>= 1) p += __shfl_xor_sync(0xffffffffu, p, off);
        if (lane == 0) s_f[o] = p + bt[o];
    }
    __syncthreads();

    // ---- final normalize + write ----
    if (w == 0) {
        float4 v = ((const float4*)s_f)[lane];
        float ss = v.x * v.x + v.y * v.y + v.z * v.z + v.w * v.w;
        #pragma unroll
        for (int off = 16; off; off >>= 1) ss += __shfl_xor_sync(0xffffffffu, ss, off);
        float rn = 1.0f / (sqrtf(ss) + 1e-12f);
        ((float4*)(outA + (size_t)b * HDIM))[lane] =
            make_float4(v.x * rn, v.y * rn, v.z * rn, v.w * rn);
    }
}

// ---------------------------------------------------------------------------
extern "C" void kernel_launch(void* const* d_in, const int* in_sizes, int n_in,
                              void* d_out, int out_size) {
    const int*   alias_ = (const int*)d_in[0];
    const int*   items  = (const int*)d_in[1];
    const int*   mask   = (const int*)d_in[2];
    const float* emb    = (const float*)d_in[3];
    const float* W0     = (const float*)d_in[4];
    const float* b0     = (const float*)d_in[5];
    const float* W1     = (const float*)d_in[6];
    const float* b1     = (const float*)d_in[7];
    const float* W2     = (const float*)d_in[8];
    const float* b2     = (const float*)d_in[9];
    const float* Wq     = (const float*)d_in[10];
    const float* bq     = (const float*)d_in[11];
    const float* Wt     = (const float*)d_in[12];
    const float* bt     = (const float*)d_in[13];
    const float* ln_g   = (const float*)d_in[14];
    const float* ln_b   = (const float*)d_in[15];

    float* out  = (float*)d_out;
    float* outA = out;                    // (1024,128)
    float* outB = out + BATCH * HDIM;     // (128,199999)

    // K0: emb row norms + transposed normalized b output (6 CTAs/SM)
    k_norm_transpose<<<NNODE / 64, 256>>>(emb, outB);

    // K1: fused a-path (2 CTAs/SM)
    const int k1_smem = 24312 * (int)sizeof(float);   // 97,248 B
    cudaFuncSetAttribute(k_fused,
                         cudaFuncAttributeMaxDynamicSharedMemorySize, k1_smem);
    k_fused<<<BATCH, 512, k1_smem>>>(alias_, items, mask, emb,
                                     W0, b0, W1, b1, W2, b2, Wq, bq,
                                     Wt, bt, ln_g, ln_b, outA);
}

// round 6
// speedup vs baseline: 2.8840x; 1.2824x over previous
#include <cuda_runtime.h>
#include <cuda_bf16.h>
#include <math.h>

#define BATCH 1024
#define LSEQ  200
#define HDIM  128
#define MAXN  201
#define NNODE 200000
#define STRIDE 132        // padded fp32 row stride (conflict-free, 16B-aligned)
#define ESTRIDE 12        // s_e row stride: float4-aligned, low-conflict
#define K1_BLOCKS 1024
#define K0_BLOCKS 3125    // 200000 / 64

// ---------------------------------------------------------------------------
// Fused kernel: blocks [0,1024) run the a-path (one per batch);
// blocks [1024,4149) row-normalize emb_W and write transposed b.T.
// Both roles are independent -> full overlap of HBM streaming with compute.
// ---------------------------------------------------------------------------
__global__ void __launch_bounds__(512, 2) k_all(
    const int* __restrict__ alias_, const int* __restrict__ items,
    const int* __restrict__ mask, const float* __restrict__ emb,
    const float* __restrict__ W0, const float* __restrict__ b0,
    const float* __restrict__ W1, const float* __restrict__ b1,
    const float* __restrict__ W2, const float* __restrict__ b2,
    const float* __restrict__ Wq, const float* __restrict__ bq,
    const float* __restrict__ Wt, const float* __restrict__ bt,
    const float* __restrict__ ln_g, const float* __restrict__ ln_b,
    float* __restrict__ outA, float* __restrict__ outB)
{
    extern __shared__ float sm[];
    int tid = threadIdx.x;
    int w = tid >> 5, lane = tid & 31;
    const float4* emb4 = (const float4*)emb;

    // ======================= K0 role: b-path =======================
    if (blockIdx.x >= K1_BLOCKS) {
        int i0 = (blockIdx.x - K1_BLOCKS) * 64;
        #pragma unroll
        for (int rr = 0; rr < 4; rr++) {
            int il = w * 4 + rr;
            int i = i0 + il;
            float4 v = emb4[(size_t)i * 32 + lane];
            float ss = v.x * v.x + v.y * v.y + v.z * v.z + v.w * v.w;
            #pragma unroll
            for (int o = 16; o; o >>= 1) ss += __shfl_xor_sync(0xffffffffu, ss, o);
            float s = 1.0f / (sqrtf(ss) + 1e-12f);
            *(float4*)&sm[il * STRIDE + lane * 4] =
                make_float4(v.x * s, v.y * s, v.z * s, v.w * s);
        }
        __syncthreads();
        for (int idx = tid; idx < 8192; idx += 512) {
            int c = idx >> 6, il = idx & 63;
            int gi = i0 + il;
            if (gi >= 1)
                __stcs(&outB[(size_t)c * (NNODE - 1) + (gi - 1)],
                       sm[il * STRIDE + c]);
        }
        return;
    }

    // ======================= K1 role: a-path =======================
    float* s_tile = sm;                    // 100*132 = 13200
    float* s_V    = sm + 13200;            // 64*132  = 8448
    float* s_e    = sm + 21648;            // 200*12  = 2400
    float* s_rn   = sm + 24048;            // 200
    int*   s_item = (int*)(sm + 24248);    // 200
    float* s_ht   = sm + 24448;            // 128
    float* s_hts  = sm + 24576;            // 128
    float* s_q0   = sm + 24704;            // 128
    float* s_vb   = sm + 24832;            // 64
    float* s_den  = sm + 24896;            // 8
    float* s_T    = sm + 24904;            // 8
    // aliases: s_tile dead after pass A; s_V dead after pass A (partials)
    float* s_S    = s_tile;                // 1024
    float* s_cat  = s_tile + 1024;         // 256
    float* s_f    = s_tile + 1280;         // 128
    __shared__ int s_len;

    int b = blockIdx.x;

    // ---- items + len (mask is a prefix: find the 1->0 edge) ----
    if (tid < LSEQ) {
        int m  = mask[b * LSEQ + tid];
        int mn = (tid < LSEQ - 1) ? mask[b * LSEQ + tid + 1] : 0;
        if (m && !mn) s_len = tid + 1;
        s_item[tid] = items[b * MAXN + alias_[b * LSEQ + tid]];
    }
    __syncthreads();
    int len = s_len;

    // ---- ht = normalized last seq row (warp 0, inline norm) ----
    if (w == 0) {
        int it = s_item[len - 1];
        float4 v = emb4[(size_t)it * 32 + lane];
        float ss = v.x * v.x + v.y * v.y + v.z * v.z + v.w * v.w;
        #pragma unroll
        for (int o = 16; o; o >>= 1) ss += __shfl_xor_sync(0xffffffffu, ss, o);
        float s = 1.0f / (sqrtf(ss) + 1e-12f);
        *(float4*)&s_ht[lane * 4] =
            make_float4(v.x * s, v.y * s, v.z * s, v.w * s);
    }
    __syncthreads();

    // ---- hts[o] = sign-ish(ht . Wq[o] + bq[o]) ----
    #pragma unroll
    for (int o = w; o < HDIM; o += 16) {
        float4 wv = ((const float4*)(Wq + o * HDIM))[lane];
        float4 xv = ((const float4*)s_ht)[lane];
        float p = wv.x * xv.x + wv.y * xv.y + wv.z * xv.z + wv.w * xv.w;
        #pragma unroll
        for (int off = 16; off; off >>= 1) p += __shfl_xor_sync(0xffffffffu, p, off);
        if (lane == 0) {
            float t = p + bq[o];
            s_hts[o] = t / (fabsf(t) + 1e-12f);
        }
    }
    __syncthreads();

    // ---- q0 = hts @ W0^T + b0 ----
    #pragma unroll
    for (int o = w; o < HDIM; o += 16) {
        float4 wv = ((const float4*)(W0 + o * HDIM))[lane];
        float4 xv = ((const float4*)s_hts)[lane];
        float p = wv.x * xv.x + wv.y * xv.y + wv.z * xv.z + wv.w * xv.w;
        #pragma unroll
        for (int off = 16; off; off >>= 1) p += __shfl_xor_sync(0xffffffffu, p, off);
        if (lane == 0) s_q0[o] = p + b0[o];
    }
    __syncthreads();

    // ---- V[h][j][c] = sum_d q0[h*16+d]*W1[j*16+d, c] ----
    for (int p = tid; p < 1024; p += 512) {       // p = (j, c)
        int j = p >> 7, c = p & 127;
        float w1d[16];
        #pragma unroll
        for (int d = 0; d < 16; d++) w1d[d] = W1[(j * 16 + d) * HDIM + c];
        #pragma unroll
        for (int h = 0; h < 8; h++) {
            float acc = 0.0f;
            #pragma unroll
            for (int d = 0; d < 16; d++) acc += s_q0[h * 16 + d] * w1d[d];
            s_V[(h * 8 + j) * STRIDE + c] = acc;
        }
    }
    if (tid < 64) {
        int h = tid >> 3, j = tid & 7;
        float acc = 0.0f;
        #pragma unroll
        for (int d = 0; d < 16; d++) acc += s_q0[h * 16 + d] * b1[j * 16 + d];
        s_vb[tid] = acc;
    }
    __syncthreads();

    // ---- pass A: two rounds of 4 heads; inline row norms; shuffle-free dots ----
    for (int t = 0; t < 2; t++) {
        for (int r = w; r < 100; r += 16) {
            int gr = t * 100 + r;
            int it = s_item[gr];
            float4 v = emb4[(size_t)it * 32 + lane];
            float ss = v.x * v.x + v.y * v.y + v.z * v.z + v.w * v.w;
            #pragma unroll
            for (int o = 16; o; o >>= 1) ss += __shfl_xor_sync(0xffffffffu, ss, o);
            float rnv = 1.0f / (sqrtf(ss) + 1e-12f);
            if (lane == 0) s_rn[gr] = rnv;
            float s = (gr < len) ? rnv : 0.0f;
            *(float4*)&s_tile[r * STRIDE + lane * 4] =
                make_float4(v.x * s, v.y * s, v.z * s, v.w * s);
        }
        __syncthreads();
        for (int idx = tid; idx < 800; idx += 512) {
            int hh = idx / 200;           // 0..3 local head
            int l  = idx % 200;
            int h  = t * 4 + hh;
            int j  = l & 7;
            const float4* sr = (const float4*)&s_tile[(hh * 25 + (l >> 3)) * STRIDE];
            const float4* vr = (const float4*)&s_V[(h * 8 + j) * STRIDE];
            float a0 = 0.f, a1 = 0.f, a2 = 0.f, a3 = 0.f;
            #pragma unroll
            for (int k = 0; k < 32; k += 4) {
                float4 x0 = sr[k + 0], y0 = vr[k + 0];
                float4 x1 = sr[k + 1], y1 = vr[k + 1];
                float4 x2 = sr[k + 2], y2 = vr[k + 2];
                float4 x3 = sr[k + 3], y3 = vr[k + 3];
                a0 += x0.x * y0.x + x0.y * y0.y + x0.z * y0.z + x0.w * y0.w;
                a1 += x1.x * y1.x + x1.y * y1.y + x1.z * y1.z + x1.w * y1.w;
                a2 += x2.x * y2.x + x2.y * y2.y + x2.z * y2.z + x2.w * y2.w;
                a3 += x3.x * y3.x + x3.y * y3.y + x3.z * y3.z + x3.w * y3.w;
            }
            float x = (a0 + a1) + (a2 + a3) + s_vb[h * 8 + j];
            float sg = 1.0f / (1.0f + __expf(-x));
            s_e[l * ESTRIDE + h] = __expf(2.0f * sg);
        }
        __syncthreads();
    }

    // ---- den (warps 0-7, all l) and masked sum T (warps 8-15), parallel ----
    if (w < 8) {
        float p = 0.0f;
        for (int l = lane; l < LSEQ; l += 32) p += s_e[l * ESTRIDE + w];
        #pragma unroll
        for (int off = 16; off; off >>= 1) p += __shfl_xor_sync(0xffffffffu, p, off);
        if (lane == 0) s_den[w] = 1.0f / p;
    } else {
        int hh = w - 8;
        float p = 0.0f;
        for (int l = lane; l < len; l += 32) p += s_e[l * ESTRIDE + hh];
        #pragma unroll
        for (int off = 16; off; off >>= 1) p += __shfl_xor_sync(0xffffffffu, p, off);
        if (lane == 0) s_T[hh] = p;
    }
    __syncthreads();
    if (tid < 8) s_T[tid] *= s_den[tid];
    // fold mask * rn[l] * (1/den[h]) into the weights
    for (int idx = tid; idx < 1600; idx += 512) {
        int l = idx >> 3, h = idx & 7;
        float m = (l < len) ? s_rn[l] : 0.0f;
        s_e[l * ESTRIDE + h] *= s_den[h] * m;
    }
    __syncthreads();

    // ---- pass B: row loaded once, applied to all 8 heads from registers ----
    {
        int lg = tid >> 6;        // 0..7 l-group
        int k2 = tid & 63;        // float2 column
        const float2* emb2 = (const float2*)emb;
        float ax[8], ay[8];
        #pragma unroll
        for (int h = 0; h < 8; h++) { ax[h] = 0.0f; ay[h] = 0.0f; }
        for (int l = lg; l < len; l += 8) {
            float2 u = __ldg(&emb2[(size_t)s_item[l] * 64 + k2]);
            float4 e0 = *(const float4*)&s_e[l * ESTRIDE];
            float4 e1 = *(const float4*)&s_e[l * ESTRIDE + 4];
            ax[0] += e0.x * u.x; ay[0] += e0.x * u.y;
            ax[1] += e0.y * u.x; ay[1] += e0.y * u.y;
            ax[2] += e0.z * u.x; ay[2] += e0.z * u.y;
            ax[3] += e0.w * u.x; ay[3] += e0.w * u.y;
            ax[4] += e1.x * u.x; ay[4] += e1.x * u.y;
            ax[5] += e1.y * u.x; ay[5] += e1.y * u.y;
            ax[6] += e1.z * u.x; ay[6] += e1.z * u.y;
            ax[7] += e1.w * u.x; ay[7] += e1.w * u.y;
        }
        float2* pp = (float2*)s_V;   // partials [lg][h][64] float2 (V is dead)
        #pragma unroll
        for (int h = 0; h < 8; h++)
            pp[lg * 512 + h * 64 + k2] = make_float2(ax[h], ay[h]);
    }
    __syncthreads();
    // reduce 8 partials -> s_S[h][k]
    {
        int h = tid >> 6, k2 = tid & 63;
        const float2* pp = (const float2*)s_V;
        float sx = 0.0f, sy = 0.0f;
        #pragma unroll
        for (int lg = 0; lg < 8; lg++) {
            float2 q = pp[lg * 512 + h * 64 + k2];
            sx += q.x; sy += q.y;
        }
        ((float2*)s_S)[h * 64 + k2] = make_float2(sx, sy);
    }
    __syncthreads();

    // ---- a[c] = W2[c,:] . S[c/16,:] + b2[c]*T[c/16]  -> s_f ----
    #pragma unroll
    for (int c = w; c < HDIM; c += 16) {
        float4 wv = ((const float4*)(W2 + c * HDIM))[lane];
        float4 sv = *(const float4*)&s_S[(c >> 4) * HDIM + lane * 4];
        float p = wv.x * sv.x + wv.y * sv.y + wv.z * sv.z + wv.w * sv.w;
        #pragma unroll
        for (int off = 16; off; off >>= 1) p += __shfl_xor_sync(0xffffffffu, p, off);
        if (lane == 0) s_f[c] = p + b2[c] * s_T[c >> 4];
    }
    __syncthreads();

    // ---- LayerNorm -> s_cat[0:128]; ht -> s_cat[128:256] ----
    if (w == 0) {
        float4 v = ((const float4*)s_f)[lane];
        float sum = v.x + v.y + v.z + v.w;
        #pragma unroll
        for (int off = 16; off; off >>= 1) sum += __shfl_xor_sync(0xffffffffu, sum, off);
        float mu = sum * (1.0f / 128.0f);
        float dx = v.x - mu, dy = v.y - mu, dz = v.z - mu, dw = v.w - mu;
        float vs = dx * dx + dy * dy + dz * dz + dw * dw;
        #pragma unroll
        for (int off = 16; off; off >>= 1) vs += __shfl_xor_sync(0xffffffffu, vs, off);
        float rstd = rsqrtf(vs * (1.0f / 128.0f) + 1e-8f);
        int c = lane * 4;
        s_cat[c + 0] = dx * rstd * ln_g[c + 0] + ln_b[c + 0];
        s_cat[c + 1] = dy * rstd * ln_g[c + 1] + ln_b[c + 1];
        s_cat[c + 2] = dz * rstd * ln_g[c + 2] + ln_b[c + 2];
        s_cat[c + 3] = dw * rstd * ln_g[c + 3] + ln_b[c + 3];
    }
    if (w == 1) {
        ((float4*)(s_cat + 128))[lane] = ((const float4*)s_ht)[lane];
    }
    __syncthreads();

    // ---- f[o] = Wt[o,:256] . cat + bt[o] ----
    #pragma unroll
    for (int o = w; o < HDIM; o += 16) {
        const float4* wr = (const float4*)(Wt + o * 256);
        float4 x0 = ((const float4*)s_cat)[lane];
        float4 w0v = wr[lane];
        float4 x1 = ((const float4*)s_cat)[lane + 32];
        float4 w1v = wr[lane + 32];
        float p = x0.x * w0v.x + x0.y * w0v.y + x0.z * w0v.z + x0.w * w0v.w
                + x1.x * w1v.x + x1.y * w1v.y + x1.z * w1v.z + x1.w * w1v.w;
        #pragma unroll
        for (int off = 16; off; off >>= 1) p += __shfl_xor_sync(0xffffffffu, p, off);
        if (lane == 0) s_f[o] = p + bt[o];
    }
    __syncthreads();

    // ---- final normalize + write ----
    if (w == 0) {
        float4 v = ((const float4*)s_f)[lane];
        float ss = v.x * v.x + v.y * v.y + v.z * v.z + v.w * v.w;
        #pragma unroll
        for (int off = 16; off; off >>= 1) ss += __shfl_xor_sync(0xffffffffu, ss, off);
        float rn = 1.0f / (sqrtf(ss) + 1e-12f);
        ((float4*)(outA + (size_t)b * HDIM))[lane] =
            make_float4(v.x * rn, v.y * rn, v.z * rn, v.w * rn);
    }
}

// ---------------------------------------------------------------------------
extern "C" void kernel_launch(void* const* d_in, const int* in_sizes, int n_in,
                              void* d_out, int out_size) {
    const int*   alias_ = (const int*)d_in[0];
    const int*   items  = (const int*)d_in[1];
    const int*   mask   = (const int*)d_in[2];
    const float* emb    = (const float*)d_in[3];
    const float* W0     = (const float*)d_in[4];
    const float* b0     = (const float*)d_in[5];
    const float* W1     = (const float*)d_in[6];
    const float* b1     = (const float*)d_in[7];
    const float* W2     = (const float*)d_in[8];
    const float* b2     = (const float*)d_in[9];
    const float* Wq     = (const float*)d_in[10];
    const float* bq     = (const float*)d_in[11];
    const float* Wt     = (const float*)d_in[12];
    const float* bt     = (const float*)d_in[13];
    const float* ln_g   = (const float*)d_in[14];
    const float* ln_b   = (const float*)d_in[15];

    float* out  = (float*)d_out;
    float* outA = out;                    // (1024,128)
    float* outB = out + BATCH * HDIM;     // (128,199999)

    const int smem_bytes = 24912 * (int)sizeof(float);   // 99,648 B
    cudaFuncSetAttribute(k_all,
                         cudaFuncAttributeMaxDynamicSharedMemorySize, smem_bytes);
    k_all<<<K1_BLOCKS + K0_BLOCKS, 512, smem_bytes>>>(
        alias_, items, mask, emb, W0, b0, W1, b1, W2, b2, Wq, bq,
        Wt, bt, ln_g, ln_b, outA, outB);
}